// round 2
// baseline (speedup 1.0000x reference)
#include <cuda_runtime.h>
#include <cuda_bf16.h>

// Problem constants (fixed by the dataset)
#define Bn   32
#define Tn   256
#define Un   128
#define Um1  127
#define Vn   4096

// ---------------- device scratch (static: no allocations allowed) ------------
__device__ float g_maxE[Bn * Tn];
__device__ float g_maxP[Bn * Un];
__device__ float g_e0  [Bn * Tn];      // emissions[b,t,0]
__device__ float g_p0  [Bn * Un];      // predictions[b,u,0]
__device__ float g_plab[Bn * Un];      // predictions[b,u,labels[b,u]]  (u < U-1)
__device__ float g_ln  [Bn * Tn * Un]; // log-norms
__device__ float g_blank[Bn * Tn * Un];
__device__ float g_lab [Bn * Tn * Um1];

// ---------------- kernel 1: per-row max over V + small gathers ---------------
// rows [0, B*T)           -> emissions rows
// rows [B*T, B*T + B*U)   -> predictions rows
__global__ void rowmax_kernel(const float* __restrict__ e,
                              const float* __restrict__ p,
                              const int*   __restrict__ labels) {
    int row  = blockIdx.x;
    bool isE = row < Bn * Tn;
    int prow = row - Bn * Tn;
    const float* base = isE ? (e + (size_t)row * Vn) : (p + (size_t)prow * Vn);

    int tid = threadIdx.x;                    // 256 threads
    const float4* b4 = (const float4*)base;
    float m = -3.4e38f;
#pragma unroll
    for (int i = 0; i < Vn / 4 / 256; i++) {  // 4 iterations
        float4 v = b4[tid + i * 256];
        m = fmaxf(m, fmaxf(fmaxf(v.x, v.y), fmaxf(v.z, v.w)));
    }
#pragma unroll
    for (int o = 16; o > 0; o >>= 1)
        m = fmaxf(m, __shfl_xor_sync(0xffffffffu, m, o));

    __shared__ float sm[8];
    if ((tid & 31) == 0) sm[tid >> 5] = m;
    __syncthreads();
    if (tid == 0) {
        float mm = sm[0];
#pragma unroll
        for (int i = 1; i < 8; i++) mm = fmaxf(mm, sm[i]);
        if (isE) {
            g_maxE[row] = mm;
            g_e0[row]   = base[0];
        } else {
            g_maxP[prow] = mm;
            g_p0[prow]   = base[0];
            int b = prow / Un, u = prow % Un;
            if (u < Um1) g_plab[prow] = base[labels[b * Um1 + u]];
        }
    }
}

// ---------------- kernel 2: fused exp-GEMM-log (log_norms) -------------------
// ln[b,t,u] = log( sum_v exp(e[b,t,v]-maxE) * exp(p[b,u,v]-maxP) ) + maxE + maxP
#define BM 64
#define BN 64
#define BK 32
__global__ __launch_bounds__(256) void gemm_kernel(const float* __restrict__ E,
                                                   const float* __restrict__ P) {
    __shared__ float As[BM][BK + 1];
    __shared__ float Bs[BN][BK + 1];

    int b  = blockIdx.z;
    int t0 = blockIdx.x * BM;
    int u0 = blockIdx.y * BN;

    const float* Ab = E + ((size_t)b * Tn + t0) * Vn;
    const float* Bb = P + ((size_t)b * Un + u0) * Vn;

    int tid = threadIdx.x;          // 256
    int tx  = tid & 15;             // 0..15  (u micro-tile)
    int ty  = tid >> 4;             // 0..15  (t micro-tile)

    // global-load mapping: 4 rows per warp, 128B contiguous per row
    int lrow = tid >> 3;            // 0..31
    int lcol = (tid & 7) * 4;       // 0..28

    float rmA0 = g_maxE[b * Tn + t0 + lrow];
    float rmA1 = g_maxE[b * Tn + t0 + lrow + 32];
    float rmB0 = g_maxP[b * Un + u0 + lrow];
    float rmB1 = g_maxP[b * Un + u0 + lrow + 32];

    const float* ap0 = Ab + (size_t)lrow * Vn + lcol;
    const float* ap1 = Ab + (size_t)(lrow + 32) * Vn + lcol;
    const float* bp0 = Bb + (size_t)lrow * Vn + lcol;
    const float* bp1 = Bb + (size_t)(lrow + 32) * Vn + lcol;

    float acc[4][4] = {};

    float4 ra0 = *(const float4*)(ap0);
    float4 ra1 = *(const float4*)(ap1);
    float4 rb0 = *(const float4*)(bp0);
    float4 rb1 = *(const float4*)(bp1);

    for (int kb = 0; kb < Vn; kb += BK) {
        // exp + store to shared (conflict-free via +1 pad, 32-bit stores)
        As[lrow][lcol + 0]      = __expf(ra0.x - rmA0);
        As[lrow][lcol + 1]      = __expf(ra0.y - rmA0);
        As[lrow][lcol + 2]      = __expf(ra0.z - rmA0);
        As[lrow][lcol + 3]      = __expf(ra0.w - rmA0);
        As[lrow + 32][lcol + 0] = __expf(ra1.x - rmA1);
        As[lrow + 32][lcol + 1] = __expf(ra1.y - rmA1);
        As[lrow + 32][lcol + 2] = __expf(ra1.z - rmA1);
        As[lrow + 32][lcol + 3] = __expf(ra1.w - rmA1);
        Bs[lrow][lcol + 0]      = __expf(rb0.x - rmB0);
        Bs[lrow][lcol + 1]      = __expf(rb0.y - rmB0);
        Bs[lrow][lcol + 2]      = __expf(rb0.z - rmB0);
        Bs[lrow][lcol + 3]      = __expf(rb0.w - rmB0);
        Bs[lrow + 32][lcol + 0] = __expf(rb1.x - rmB1);
        Bs[lrow + 32][lcol + 1] = __expf(rb1.y - rmB1);
        Bs[lrow + 32][lcol + 2] = __expf(rb1.z - rmB1);
        Bs[lrow + 32][lcol + 3] = __expf(rb1.w - rmB1);
        __syncthreads();

        // prefetch next K-chunk into registers (hides global latency)
        if (kb + BK < Vn) {
            ra0 = *(const float4*)(ap0 + kb + BK);
            ra1 = *(const float4*)(ap1 + kb + BK);
            rb0 = *(const float4*)(bp0 + kb + BK);
            rb1 = *(const float4*)(bp1 + kb + BK);
        }

#pragma unroll
        for (int k = 0; k < BK; k++) {
            float af[4], bf[4];
#pragma unroll
            for (int i = 0; i < 4; i++) af[i] = As[ty * 4 + i][k];
#pragma unroll
            for (int j = 0; j < 4; j++) bf[j] = Bs[tx * 4 + j][k];
#pragma unroll
            for (int i = 0; i < 4; i++)
#pragma unroll
                for (int j = 0; j < 4; j++) acc[i][j] += af[i] * bf[j];
        }
        __syncthreads();
    }

    // epilogue: ln = log(acc) + maxE + maxP, vectorized along u
#pragma unroll
    for (int i = 0; i < 4; i++) {
        int t = t0 + ty * 4 + i;
        float mE = g_maxE[b * Tn + t];
        float4 o;
        float mP0 = g_maxP[b * Un + u0 + tx * 4 + 0];
        float mP1 = g_maxP[b * Un + u0 + tx * 4 + 1];
        float mP2 = g_maxP[b * Un + u0 + tx * 4 + 2];
        float mP3 = g_maxP[b * Un + u0 + tx * 4 + 3];
        o.x = logf(acc[i][0]) + mE + mP0;
        o.y = logf(acc[i][1]) + mE + mP1;
        o.z = logf(acc[i][2]) + mE + mP2;
        o.w = logf(acc[i][3]) + mE + mP3;
        *(float4*)&g_ln[((size_t)b * Tn + t) * Un + u0 + tx * 4] = o;
    }
}

// ---------------- kernel 3: blank/label log-probs ----------------------------
__global__ void prep_kernel(const float* __restrict__ E,
                            const int*   __restrict__ labels) {
    int t = blockIdx.x;
    int b = blockIdx.y;
    int u = threadIdx.x;              // 128

    __shared__ int labs[Um1];
    if (u < Um1) labs[u] = labels[b * Um1 + u];
    __syncthreads();

    size_t base = ((size_t)b * Tn + t) * Un;
    float lnv = g_ln[base + u];
    g_blank[base + u] = g_e0[b * Tn + t] + g_p0[b * Un + u] - lnv;
    if (u < Um1) {
        float elab = E[((size_t)b * Tn + t) * Vn + labs[u]];
        g_lab[((size_t)b * Tn + t) * Um1 + u] = elab + g_plab[b * Un + u] - lnv;
    }
}

// ---------------- kernel 4: wavefront DP over the (T,U) lattice --------------
// alpha[t,u] = lse(alpha[t-1,u]+blank[t-1,u], alpha[t,u-1]+lab[t,u-1])
// processed along anti-diagonals d = t+u, lane u per thread.
__global__ void dp_kernel(const int* __restrict__ ilen,
                          const int* __restrict__ llen,
                          float* __restrict__ out) {
    const float NEG = -1e30f;
    int b = blockIdx.x;
    int u = threadIdx.x;              // 128

    const float* blank = g_blank + (size_t)b * Tn * Un;
    const float* lab   = g_lab   + (size_t)b * Tn * Um1;

    __shared__ float Abuf[2][Un];
    Abuf[0][u] = (u == 0) ? 0.0f : NEG;   // diagonal d = 0: only cell (0,0)

    int Tl = ilen[b], Ul = llen[b];
    int dfin = Tl - 1 + Ul;
    __syncthreads();

    // 2-deep fetch pipeline for the diagonal operands
    float bv0 = 0.f, lv0 = 0.f, bv1 = 0.f, lv1 = 0.f;
    {
        int t = 1 - u;
        if (t >= 1 && t < Tn) bv0 = blank[(t - 1) * Un + u];
        if (u >= 1 && t >= 0 && t < Tn) lv0 = lab[t * Um1 + (u - 1)];
        t = 2 - u;
        if (t >= 1 && t < Tn) bv1 = blank[(t - 1) * Un + u];
        if (u >= 1 && t >= 0 && t < Tn) lv1 = lab[t * Um1 + (u - 1)];
    }

    int cur = 0;
    for (int d = 1; d <= Tn + Un - 2; d++) {
        float ap  = Abuf[cur][u];
        float apm = (u > 0) ? Abuf[cur][u - 1] : NEG;
        int t = d - u;
        float a = NEG;
        if (t >= 0 && t < Tn) {
            float vert  = (t >= 1) ? (ap  + bv0) : NEG;
            float horiz = (u >= 1) ? (apm + lv0) : NEG;
            float m = fmaxf(vert, horiz);
            a = m + log1pf(__expf(fminf(vert, horiz) - m));
        }
        Abuf[cur ^ 1][u] = a;
        if (d == dfin && u == Ul)
            out[b] = -(a + blank[(Tl - 1) * Un + Ul]);

        // rotate pipeline, fetch d+2
        bv0 = bv1; lv0 = lv1;
        bv1 = 0.f; lv1 = 0.f;
        int tn = d + 2 - u;
        if (tn >= 1 && tn < Tn) bv1 = blank[(tn - 1) * Un + u];
        if (u >= 1 && tn >= 0 && tn < Tn) lv1 = lab[tn * Um1 + (u - 1)];

        cur ^= 1;
        __syncthreads();
    }
}

// ---------------- launcher ---------------------------------------------------
extern "C" void kernel_launch(void* const* d_in, const int* in_sizes, int n_in,
                              void* d_out, int out_size) {
    const float* e      = (const float*)d_in[0];
    const float* p      = (const float*)d_in[1];
    const int*   labels = (const int*)  d_in[2];
    const int*   ilen   = (const int*)  d_in[3];
    const int*   llen   = (const int*)  d_in[4];
    float* out = (float*)d_out;

    rowmax_kernel<<<Bn * Tn + Bn * Un, 256>>>(e, p, labels);
    gemm_kernel<<<dim3(Tn / BM, Un / BN, Bn), 256>>>(e, p);
    prep_kernel<<<dim3(Tn, Bn), 128>>>(e, labels);
    dp_kernel<<<Bn, Un>>>(ilen, llen, out);
}

// round 4
// speedup vs baseline: 1.6521x; 1.6521x over previous
#include <cuda_runtime.h>
#include <cuda_bf16.h>
#include <cstdint>

// Problem constants
#define Bn   32
#define Tn   256
#define Un   128
#define Um1  127
#define Vn   4096
#define ND   383            // number of anti-diagonals (Tn+Un-1)

// ---------------- device scratch ---------------------------------------------
__device__ __align__(16) __nv_bfloat16 g_expE[(size_t)Bn * Tn * Vn]; // exp(E) bf16
__device__ __align__(16) __nv_bfloat16 g_expP[(size_t)Bn * Un * Vn]; // exp(P) bf16
__device__ __align__(16) float gd_blank[(size_t)Bn * ND * 128]; // diag-major blank_lp
__device__ __align__(16) float gd_lab  [(size_t)Bn * ND * 128]; // diag-major lab_lp

// ---------------- PTX helpers ------------------------------------------------
__device__ __forceinline__ uint32_t smem_u32(const void* p) {
    uint32_t a;
    asm("{ .reg .u64 t; cvta.to.shared.u64 t, %1; cvt.u32.u64 %0, t; }"
        : "=r"(a) : "l"(p));
    return a;
}
#define CP16(dst, src)   asm volatile("cp.async.cg.shared.global [%0], [%1], 16;" :: "r"(dst), "l"(src) : "memory")
#define CP_COMMIT()      asm volatile("cp.async.commit_group;" ::: "memory")

#define LDSM4(r0, r1, r2, r3, addr) \
    asm volatile("ldmatrix.sync.aligned.m8n8.x4.shared.b16 {%0,%1,%2,%3}, [%4];" \
        : "=r"(r0), "=r"(r1), "=r"(r2), "=r"(r3) : "r"(addr))

#define MMA16816(c, a, bq) \
    asm volatile("mma.sync.aligned.m16n8k16.row.col.f32.bf16.bf16.f32 " \
        "{%0,%1,%2,%3}, {%4,%5,%6,%7}, {%8,%9}, {%0,%1,%2,%3};" \
        : "+f"((c)[0]), "+f"((c)[1]), "+f"((c)[2]), "+f"((c)[3]) \
        : "r"((a)[0]), "r"((a)[1]), "r"((a)[2]), "r"((a)[3]), \
          "r"((bq)[0]), "r"((bq)[1]))

// ---------------- kernel 1: exp + bf16 convert (no max shift needed) ---------
__global__ void expcvt_kernel(const float* __restrict__ E,
                              const float* __restrict__ P) {
    const size_t NE = (size_t)Bn * Tn * Vn;
    size_t i = ((size_t)blockIdx.x * 256 + threadIdx.x) * 8;
    const float* src;
    __nv_bfloat16* dst;
    if (i < NE) { src = E + i; dst = g_expE + i; }
    else        { src = P + (i - NE); dst = g_expP + (i - NE); }
    float4 v0 = *(const float4*)(src);
    float4 v1 = *(const float4*)(src + 4);
    __nv_bfloat162 o[4];
    o[0] = __floats2bfloat162_rn(__expf(v0.x), __expf(v0.y));
    o[1] = __floats2bfloat162_rn(__expf(v0.z), __expf(v0.w));
    o[2] = __floats2bfloat162_rn(__expf(v1.x), __expf(v1.y));
    o[3] = __floats2bfloat162_rn(__expf(v1.z), __expf(v1.w));
    uint4 pk;
    pk.x = *(uint32_t*)&o[0]; pk.y = *(uint32_t*)&o[1];
    pk.z = *(uint32_t*)&o[2]; pk.w = *(uint32_t*)&o[3];
    *(uint4*)dst = pk;
}

// ---------------- kernel 2: HMMA GEMM + fused epilogue -----------------------
// CTA tile: 64(t) x 128(u); K = 4096 in 64 chunks of BK=64 (128B rows).
// 8 warps as 2(m) x 4(n); warp tile 32x32 via mma.m16n8k16.
// smem per stage: A 64x128B = 8KB, B 128x128B = 16KB -> 24KB; 4 stages.
#define SMEM_HDR  2048
#define STAGE_B   24576
#define SMEM_TOT  (SMEM_HDR + 4 * STAGE_B)   // 100352

__global__ __launch_bounds__(256, 1) void gemm_kernel(const float* __restrict__ E,
                                                      const float* __restrict__ P,
                                                      const int* __restrict__ labels) {
    extern __shared__ __align__(1024) char smem[];
    uint32_t sb = smem_u32(smem);
    float* p0s = (float*)(smem);
    float* pls = (float*)(smem + 512);
    int*   lbs = (int*)(smem + 1024);

    int tid = threadIdx.x, lane = tid & 31, wid = tid >> 5;
    int wm = wid >> 2;              // 0..1  (m group of 32 rows)
    int wn = wid & 3;               // 0..3  (n group of 32 cols)
    int t0 = blockIdx.x * 64;
    int b  = blockIdx.y;

    // header: p0, p_lab, labels for this batch
    if (tid < Un) {
        const float* Pr = P + (size_t)(b * Un + tid) * Vn;
        p0s[tid] = Pr[0];
        if (tid < Um1) {
            int l = labels[b * Um1 + tid];
            lbs[tid] = l;
            pls[tid] = Pr[l];
        }
    }

    // cp.async producer: thread -> (row = tid>>3 [+32k], chunk = tid&7)
    auto issue = [&](int k) {
        uint32_t base = sb + SMEM_HDR + (k & 3) * STAGE_B;
        int r = tid >> 3, c = tid & 7;
        uint32_t sw = (uint32_t)((c ^ (r & 7)) << 4);
        const __nv_bfloat16* asrc = g_expE + (size_t)(b * Tn + t0 + r) * Vn + k * 64 + c * 8;
        CP16(base + r * 128 + sw,        asrc);
        CP16(base + (r + 32) * 128 + sw, asrc + (size_t)32 * Vn);
        const __nv_bfloat16* bsrc = g_expP + (size_t)(b * Un + r) * Vn + k * 64 + c * 8;
        uint32_t bb = base + 8192;
#pragma unroll
        for (int q = 0; q < 4; q++)
            CP16(bb + (r + q * 32) * 128 + sw, bsrc + (size_t)(q * 32) * Vn);
        CP_COMMIT();
    };

    issue(0); issue(1); issue(2);

    float cr[2][4][4] = {};

    for (int k = 0; k < 64; k++) {
        if (k <= 60) asm volatile("cp.async.wait_group 2;" ::: "memory");
        else         asm volatile("cp.async.wait_group 0;" ::: "memory");
        __syncthreads();
        if (k + 3 < 64) issue(k + 3);

        uint32_t sA = sb + SMEM_HDR + (k & 3) * STAGE_B;
        uint32_t sB = sA + 8192;
#pragma unroll
        for (int kf = 0; kf < 4; kf++) {
            uint32_t afr[2][4], bfr[4][2];
#pragma unroll
            for (int mi = 0; mi < 2; mi++) {
                int row = wm * 32 + mi * 16 + (lane & 15);
                int kc  = kf * 2 + (lane >> 4);
                uint32_t ad = sA + row * 128 + (((uint32_t)(kc ^ (row & 7))) << 4);
                LDSM4(afr[mi][0], afr[mi][1], afr[mi][2], afr[mi][3], ad);
            }
#pragma unroll
            for (int p = 0; p < 2; p++) {
                int g = lane >> 3;
                int nrow = wn * 32 + p * 16 + ((g >> 1) << 3) + (lane & 7);
                int kc   = kf * 2 + (g & 1);
                uint32_t bd = sB + nrow * 128 + (((uint32_t)(kc ^ (nrow & 7))) << 4);
                uint32_t r0, r1, r2, r3;
                LDSM4(r0, r1, r2, r3, bd);
                bfr[p * 2 + 0][0] = r0; bfr[p * 2 + 0][1] = r1;
                bfr[p * 2 + 1][0] = r2; bfr[p * 2 + 1][1] = r3;
            }
#pragma unroll
            for (int mi = 0; mi < 2; mi++)
#pragma unroll
                for (int ni = 0; ni < 4; ni++)
                    MMA16816(cr[mi][ni], afr[mi], bfr[ni]);
        }
    }

    // ---- epilogue: ln = log(acc); blank/lab in diagonal-major layout --------
    float* gbd = gd_blank + (size_t)b * ND * 128;
    float* gld = gd_lab   + (size_t)b * ND * 128;
#pragma unroll
    for (int mi = 0; mi < 2; mi++) {
#pragma unroll
        for (int h = 0; h < 2; h++) {
            int t = t0 + wm * 32 + mi * 16 + h * 8 + (lane >> 2);
            const float* Er = E + (size_t)(b * Tn + t) * Vn;
            float e0 = Er[0];
#pragma unroll
            for (int ni = 0; ni < 4; ni++) {
#pragma unroll
                for (int j = 0; j < 2; j++) {
                    int u = wn * 32 + ni * 8 + (lane & 3) * 2 + j;
                    float ln = __logf(cr[mi][ni][h * 2 + j]);
                    gbd[(t + u) * 128 + u] = e0 + p0s[u] - ln;
                    if (u < Um1)
                        gld[(t + u) * 128 + u] = Er[lbs[u]] + pls[u] - ln;
                }
            }
        }
    }
}

// ---------------- kernel 3: register-wavefront DP (1 warp / batch) -----------
// Thread owns u = lane*4 .. lane*4+3; alpha in registers; shfl for u-1 neighbor.
// Diagonal d needs row d-1 of the diag-major operand arrays.
__device__ __forceinline__ float lse_cell(int d, int u, float a_u, float a_um1,
                                          float bvv, float lvv) {
    const float NEG = -1e30f;
    int t = d - u;
    if (t < 0 || t > Tn - 1) return NEG;
    float v = (t >= 1) ? (a_u + bvv) : NEG;
    float h = (u >= 1) ? (a_um1 + lvv) : NEG;
    float m = fmaxf(v, h);
    float z = fminf(v, h) - m;
    return m + __logf(1.0f + __expf(z));
}

__global__ void dp_kernel(const int* __restrict__ ilen,
                          const int* __restrict__ llen,
                          float* __restrict__ out) {
    const float NEG = -1e30f;
    int b = blockIdx.x;
    int lane = threadIdx.x;          // 32
    const float* gb = gd_blank + (size_t)b * ND * 128;
    const float* gl = gd_lab   + (size_t)b * ND * 128;
    int Tl = ilen[b], Ul = llen[b];
    int dfin = Tl - 1 + Ul;
    int u0 = lane * 4;
    bool owner = (u0 <= Ul) && (Ul < u0 + 4);
    float bfin = gb[dfin * 128 + Ul];    // blank_lp[Tl-1, Ul]

    float a0 = (u0 == 0) ? 0.0f : NEG, a1 = NEG, a2 = NEG, a3 = NEG;

    float4 pb[8], pl[8];
#pragma unroll
    for (int s = 0; s < 8; s++) {        // operands for diagonals 1..8 (rows 0..7)
        pb[s] = *(const float4*)&gb[s * 128 + u0];
        pl[s] = *(const float4*)&gl[s * 128 + u0];
    }

    for (int d0 = 1; d0 <= 382; d0 += 8) {
#pragma unroll
        for (int ss = 0; ss < 8; ss++) {
            int d = d0 + ss;
            if (d > 382) break;
            float4 bv = pb[ss], lv = pl[ss];
            int nr = d + 7; if (nr > 381) nr = 381;   // row for diag d+8
            pb[ss] = *(const float4*)&gb[nr * 128 + u0];
            pl[ss] = *(const float4*)&gl[nr * 128 + u0];

            float am1 = __shfl_up_sync(0xffffffffu, a3, 1);   // alpha[u0-1]
            float lm1 = __shfl_up_sync(0xffffffffu, lv.w, 1); // lab[u0-1]

            float n0 = lse_cell(d, u0 + 0, a0, am1, bv.x, lm1);
            float n1 = lse_cell(d, u0 + 1, a1, a0,  bv.y, lv.x);
            float n2 = lse_cell(d, u0 + 2, a2, a1,  bv.z, lv.y);
            float n3 = lse_cell(d, u0 + 3, a3, a2,  bv.w, lv.z);
            a0 = n0; a1 = n1; a2 = n2; a3 = n3;

            if (d == dfin && owner) {
                int j = Ul & 3;
                float av = (j == 0) ? n0 : (j == 1) ? n1 : (j == 2) ? n2 : n3;
                out[b] = -(av + bfin);
            }
        }
    }
}

// ---------------- launcher ---------------------------------------------------
extern "C" void kernel_launch(void* const* d_in, const int* in_sizes, int n_in,
                              void* d_out, int out_size) {
    const float* e      = (const float*)d_in[0];
    const float* p      = (const float*)d_in[1];
    const int*   labels = (const int*)  d_in[2];
    const int*   ilen   = (const int*)  d_in[3];
    const int*   llen   = (const int*)  d_in[4];
    float* out = (float*)d_out;

    cudaFuncSetAttribute(gemm_kernel,
                         cudaFuncAttributeMaxDynamicSharedMemorySize, SMEM_TOT);

    // total elems = B*T*V + B*U*V = 50331648 ; / (256 threads * 8 elems) = 24576
    expcvt_kernel<<<24576, 256>>>(e, p);
    gemm_kernel<<<dim3(4, Bn), 256, SMEM_TOT>>>(e, p, labels);
    dp_kernel<<<Bn, 32>>>(ilen, llen, out);
}